// round 16
// baseline (speedup 1.0000x reference)
#include <cuda_runtime.h>
#include <math.h>

#define NN 100000
#define EE 1000000
#define NB1 98     // ceil(NN/1024)
#define GOUT 1184  // grid for k_out (≈8 blocks/SM for latency hiding)

typedef unsigned long long ull;

// ---------------- scratch (static device globals; no allocation) -------------
__device__ float  g_z[(size_t)NN*128];     // aggregated per-head features
__device__ float  g_buf64[(size_t)NN*64];  // layer output (pre-BN)
__device__ float  g_x64[(size_t)NN*64];    // normalized features x' (layers 2,3)
__device__ float  g_as[NN*2];              // per-node src scores
__device__ float4 g_att[NN];               // (as0, as1, ad0, ad1) per node
__device__ int    g_deg[NN];               // zero-init; re-zeroed by k_scatter
__device__ int    g_off[NN];
__device__ int    g_cursor[NN];
__device__ int    g_esrc[EE];
__device__ int    g_bsum[128];
__device__ float  g_part[GOUT*128];        // BN partials per k_out block
__device__ float  g_bnscale[64];
__device__ float  g_bnshift[64];
__device__ int    g_bncnt;
__device__ int    g_scancnt;
__device__ int    g_scandone;

__device__ __forceinline__ float lrelu(float v){ return v > 0.f ? v : 0.2f*v; }

__device__ __forceinline__ ull pk2(float lo, float hi){
  ull u; asm("mov.b64 %0, {%1, %2};" : "=l"(u) : "f"(lo), "f"(hi)); return u;
}
__device__ __forceinline__ void upk2(float& lo, float& hi, ull u){
  asm("mov.b64 {%0, %1}, %2;" : "=f"(lo), "=f"(hi) : "l"(u));
}
#define FMA2(d, a, b, c) \
  asm("fma.rn.f32x2 %0, %1, %2, %3;" : "=l"(d) : "l"(a), "l"(b), "l"(c))

// ---------------- fused: degree count + layer-1 attention scores -------------
__global__ void __launch_bounds__(256) k_attcount(const int* __restrict__ ei,
                                                  const float* __restrict__ x,
                                                  const float* __restrict__ W,
                                                  const float* __restrict__ as_,
                                                  const float* __restrict__ ad_){
  __shared__ float swa[2][16], swd[2][16];
  int tid = threadIdx.x;
  int e = blockIdx.x*blockDim.x + tid;
  bool doatt = (e < NN);
  if (doatt && tid < 64){
    int h = (tid >> 4) & 1;
    int k = tid & 15;
    const float* att = (tid < 32) ? as_ : ad_;
    const float* wrow = W + k*128 + h*64;
    float acc = 0.f;
    #pragma unroll 16
    for (int c = 0; c < 64; c++) acc += wrow[c]*att[h*64 + c];
    if (tid < 32) swa[h][k] = acc; else swd[h][k] = acc;
  }
  if (e < EE) atomicAdd(&g_deg[ei[EE + e]], 1);
  if (!doatt) return;
  __syncthreads();
  int n = e;
  float s0 = 0.f, s1 = 0.f, d0 = 0.f, d1 = 0.f;
  const float4* xr = (const float4*)(x + (size_t)n*16);
  #pragma unroll
  for (int q = 0; q < 4; q++){
    float4 v = xr[q];
    int k = 4*q;
    s0 += v.x*swa[0][k] + v.y*swa[0][k+1] + v.z*swa[0][k+2] + v.w*swa[0][k+3];
    s1 += v.x*swa[1][k] + v.y*swa[1][k+1] + v.z*swa[1][k+2] + v.w*swa[1][k+3];
    d0 += v.x*swd[0][k] + v.y*swd[0][k+1] + v.z*swd[0][k+2] + v.w*swd[0][k+3];
    d1 += v.x*swd[1][k] + v.y*swd[1][k+1] + v.z*swd[1][k+2] + v.w*swd[1][k+3];
  }
  ((float2*)g_as)[n] = make_float2(s0, s1);
  g_att[n] = make_float4(s0, s1, d0, d1);
}

// ---------------- fused scan: local scan + spin-wait grid sync + prefix ------
__global__ void __launch_bounds__(256) k_scanall(){
  __shared__ int s[256];
  __shared__ int swarp[8];
  int tid = threadIdx.x;
  int b = blockIdx.x;
  int base = b*1024 + tid*4;
  int v[4]; int loc = 0;
  #pragma unroll
  for (int i = 0; i < 4; i++){ int idx = base + i; v[i] = (idx < NN) ? g_deg[idx] : 0; loc += v[i]; }
  s[tid] = loc; __syncthreads();
  #pragma unroll
  for (int d = 1; d < 256; d <<= 1){
    int t = (tid >= d) ? s[tid-d] : 0; __syncthreads();
    s[tid] += t; __syncthreads();
  }
  int run = (tid == 0) ? 0 : s[tid-1];
  #pragma unroll
  for (int i = 0; i < 4; i++){ run += v[i]; int idx = base + i; if (idx < NN) g_off[idx] = run; }
  if (tid == 255){
    g_bsum[b] = s[255];
    __threadfence();
    atomicAdd(&g_scancnt, 1);
  }
  if (tid == 0){
    while (atomicAdd(&g_scancnt, 0) < NB1) { }
  }
  __syncthreads();
  {
    int vv = (tid < b) ? g_bsum[tid] : 0;
    #pragma unroll
    for (int o = 16; o; o >>= 1) vv += __shfl_xor_sync(0xffffffffu, vv, o);
    if ((tid & 31) == 0) swarp[tid >> 5] = vv;
  }
  __syncthreads();
  int pre = swarp[0] + swarp[1] + swarp[2] + swarp[3];
  #pragma unroll
  for (int i = 0; i < 4; i++){
    int idx = base + i;
    if (idx < NN){
      int off = g_off[idx] + pre;
      g_off[idx] = off;
      g_cursor[idx] = off - g_deg[idx];
    }
  }
  __syncthreads();
  if (tid == 0){
    int d = atomicAdd(&g_scandone, 1);
    if (d == NB1-1){ g_scancnt = 0; g_scandone = 0; }
  }
}

__global__ void k_scatter(const int* __restrict__ ei){
  int e = blockIdx.x*blockDim.x + threadIdx.x;
  if (e < EE){
    int s = ei[e], d = ei[EE + e];
    int pos = atomicAdd(&g_cursor[d], 1);
    g_esrc[pos] = s;
  }
  if (e < NN) g_deg[e] = 0;
}

// ---------------- attention scores (layers 2,3): thread-per-node, BN in regs -
// Also writes the normalized x' row to g_x64 for the BN-free gather.
__global__ void __launch_bounds__(256) k_att2(const float* __restrict__ W,
                                              const float* __restrict__ as_,
                                              const float* __restrict__ ad_){
  __shared__ float swa[2][64], swd[2][64];
  __shared__ float sbs[64], sbh[64];
  int tid = threadIdx.x;
  {
    int h = (tid >> 6) & 1;
    int k = tid & 63;
    const float* att = (tid < 128) ? as_ : ad_;
    const float* wrow = W + k*128 + h*64;
    float acc = 0.f;
    #pragma unroll 16
    for (int c = 0; c < 64; c++) acc += wrow[c]*att[h*64 + c];
    if (tid < 128) swa[h][k] = acc; else swd[h][k] = acc;
    if (tid < 64){ sbs[tid] = g_bnscale[tid]; sbh[tid] = g_bnshift[tid]; }
  }
  __syncthreads();
  int n = blockIdx.x*blockDim.x + tid;
  if (n >= NN) return;
  float s0 = 0.f, s1 = 0.f, d0 = 0.f, d1 = 0.f;
  const float4* xr = (const float4*)(g_buf64 + (size_t)n*64);
  float4* xw = (float4*)(g_x64 + (size_t)n*64);
  #pragma unroll
  for (int q = 0; q < 16; q++){
    float4 v = xr[q];
    int k = 4*q;
    v.x = fmaxf(fmaf(v.x, sbs[k],   sbh[k]),   0.f);
    v.y = fmaxf(fmaf(v.y, sbs[k+1], sbh[k+1]), 0.f);
    v.z = fmaxf(fmaf(v.z, sbs[k+2], sbh[k+2]), 0.f);
    v.w = fmaxf(fmaf(v.w, sbs[k+3], sbh[k+3]), 0.f);
    xw[q] = v;
    s0 += v.x*swa[0][k] + v.y*swa[0][k+1] + v.z*swa[0][k+2] + v.w*swa[0][k+3];
    s1 += v.x*swa[1][k] + v.y*swa[1][k+1] + v.z*swa[1][k+2] + v.w*swa[1][k+3];
    d0 += v.x*swd[0][k] + v.y*swd[0][k+1] + v.z*swd[0][k+2] + v.w*swd[0][k+3];
    d1 += v.x*swd[1][k] + v.y*swd[1][k+1] + v.z*swd[1][k+2] + v.w*swd[1][k+3];
  }
  ((float2*)g_as)[n] = make_float2(s0, s1);
  g_att[n] = make_float4(s0, s1, d0, d1);
}

// ---------------- GAT aggregation: single-pass softmax, smem-staged triples,
//                  FIXED 16-iter unrolled gather -----------------------------
__global__ void __launch_bounds__(256) k_agg16(const float* __restrict__ x){
  __shared__ __align__(16) float4 sedge[16][16];
  int t = blockIdx.x*blockDim.x + threadIdx.x;
  int n = t >> 4, lane = t & 15;
  if (n >= NN) return;
  const unsigned gm = 0xFFFFu << (threadIdx.x & 16);
  int grp = threadIdx.x >> 4;
  int start = n ? g_off[n-1] : 0;
  int end   = g_off[n];
  float4 attn = g_att[n];
  float ad0 = attn.z, ad1 = attn.w;
  float es0 = lrelu(attn.x + ad0);
  float es1 = lrelu(attn.y + ad1);
  float vs = x[(size_t)n*16 + lane];
  ull y01 = pk2(vs, vs);
  float dacc0 = 0.f, dacc1 = 0.f;

  for (int base = start; base < end; base += 16){
    int cnt = min(16, end - base);
    int s = n; float w0 = 0.f, w1 = 0.f;
    if (lane < cnt){
      s = g_esrc[base + lane];
      float2 a = ((const float2*)g_as)[s];
      w0 = __expf(lrelu(a.x + ad0) - es0);
      w1 = __expf(lrelu(a.y + ad1) - es1);
      dacc0 += w0; dacc1 += w1;
    }
    sedge[grp][lane] = make_float4(__int_as_float(s), w0, w1, 0.f);
    __syncwarp(gm);
    #pragma unroll
    for (int k = 0; k < 16; k++){
      float4 tr = sedge[grp][k];
      int sk = __float_as_int(tr.x);
      float v = x[(size_t)sk*16 + lane];
      FMA2(y01, pk2(v, v), pk2(tr.y, tr.z), y01);
    }
    __syncwarp(gm);
  }
  #pragma unroll
  for (int o = 8; o; o >>= 1){
    dacc0 += __shfl_xor_sync(gm, dacc0, o, 16);
    dacc1 += __shfl_xor_sync(gm, dacc1, o, 16);
  }
  float den0 = 1.f + dacc0 + 1e-16f;
  float den1 = 1.f + dacc1 + 1e-16f;
  float y0, y1; upk2(y0, y1, y01);
  float* zr = g_z + (size_t)n*32;
  zr[lane]      = y0/den0;
  zr[16 + lane] = y1/den1;
}

__global__ void __launch_bounds__(256) k_agg64(){
  __shared__ __align__(16) float4 sedge[16][16];
  int t = blockIdx.x*blockDim.x + threadIdx.x;
  int n = t >> 4, lane = t & 15;
  if (n >= NN) return;
  const unsigned gm = 0xFFFFu << (threadIdx.x & 16);
  int grp = threadIdx.x >> 4;
  int start = n ? g_off[n-1] : 0;
  int end   = g_off[n];
  float4 attn = g_att[n];
  float ad0 = attn.z, ad1 = attn.w;
  float es0 = lrelu(attn.x + ad0);
  float es1 = lrelu(attn.y + ad1);
  ulonglong2 vsl = ((const ulonglong2*)(g_x64 + (size_t)n*64))[lane];
  ull y0a = vsl.x, y0b = vsl.y;
  ull y1a = vsl.x, y1b = vsl.y;
  float dacc0 = 0.f, dacc1 = 0.f;

  for (int base = start; base < end; base += 16){
    int cnt = min(16, end - base);
    int s = n; float w0 = 0.f, w1 = 0.f;
    if (lane < cnt){
      s = g_esrc[base + lane];
      float2 a = ((const float2*)g_as)[s];
      w0 = __expf(lrelu(a.x + ad0) - es0);
      w1 = __expf(lrelu(a.y + ad1) - es1);
      dacc0 += w0; dacc1 += w1;
    }
    sedge[grp][lane] = make_float4(__int_as_float(s), w0, w1, 0.f);
    __syncwarp(gm);
    #pragma unroll 4
    for (int k = 0; k < 16; k++){
      float4 tr = sedge[grp][k];
      int sk = __float_as_int(tr.x);
      ull w0p = pk2(tr.y, tr.y);
      ull w1p = pk2(tr.z, tr.z);
      ulonglong2 v = ((const ulonglong2*)(g_x64 + (size_t)sk*64))[lane];
      FMA2(y0a, v.x, w0p, y0a); FMA2(y0b, v.y, w0p, y0b);
      FMA2(y1a, v.x, w1p, y1a); FMA2(y1b, v.y, w1p, y1b);
    }
    __syncwarp(gm);
  }
  #pragma unroll
  for (int o = 8; o; o >>= 1){
    dacc0 += __shfl_xor_sync(gm, dacc0, o, 16);
    dacc1 += __shfl_xor_sync(gm, dacc1, o, 16);
  }
  float den0 = 1.f + dacc0 + 1e-16f;
  float den1 = 1.f + dacc1 + 1e-16f;
  float i0 = 1.f/den0, i1 = 1.f/den1;
  float l, h;
  float4 o0, o1;
  upk2(l, h, y0a); o0.x = l*i0; o0.y = h*i0;
  upk2(l, h, y0b); o0.z = l*i0; o0.w = h*i0;
  upk2(l, h, y1a); o1.x = l*i1; o1.y = h*i1;
  upk2(l, h, y1b); o1.z = l*i1; o1.w = h*i1;
  float4* zr = (float4*)(g_z + (size_t)n*128);
  zr[lane]      = o0;
  zr[16 + lane] = o1;
}

// ---------------- output transform: 8 nodes per barrier pair (R13 design) ----
template<int D>
__global__ void __launch_bounds__(256) k_out(const float* __restrict__ W,
                                             const float* __restrict__ b,
                                             const float* __restrict__ gam,
                                             const float* __restrict__ bet){
  int tid = threadIdx.x;
  int g   = tid >> 7;
  int idx = tid & 127;
  int j   = idx >> 1;
  int hb  = idx & 1;
  ull wp[D/2];
  #pragma unroll
  for (int k2 = 0; k2 < D/2; k2++)
    wp[k2] = pk2(0.5f*W[(2*k2)*128 + hb*64 + j], 0.5f*W[(2*k2+1)*128 + hb*64 + j]);
  float bj = b[j];
  __shared__ __align__(16) float sy[8][2*D];
  __shared__ float sacc[256];
  float bs = 0.f, bq = 0.f;
  const int F4 = D/2;
  for (int n0 = blockIdx.x*8; n0 < NN; n0 += GOUT*8){
    if (tid < 4*D){
      int row = tid / F4;
      int col = tid % F4;
      int n = n0 + row;
      if (n < NN)
        ((float4*)sy[row])[col] = ((const float4*)(g_z + (size_t)n*(2*D)))[col];
    }
    __syncthreads();
    #pragma unroll
    for (int i = 0; i < 4; i++){
      int n = n0 + g*4 + i;
      const ull* yp = (const ull*)(sy[g*4+i] + hb*D);
      ull a0 = 0ull, a1 = 0ull;
      #pragma unroll
      for (int k2 = 0; k2 < D/2; k2 += 2){
        FMA2(a0, yp[k2],   wp[k2],   a0);
        FMA2(a1, yp[k2+1], wp[k2+1], a1);
      }
      float l0,h0,l1,h1; upk2(l0,h0,a0); upk2(l1,h1,a1);
      float partial = (l0+h0)+(l1+h1);
      float comb = partial + __shfl_xor_sync(0xffffffffu, partial, 1);
      if (hb == 0 && n < NN){
        float r = comb + bj;
        g_buf64[(size_t)n*64 + j] = r;
        bs += r; bq += r*r;
      }
    }
    __syncthreads();
  }
  sacc[tid] = bs;
  __syncthreads();
  float ts = 0.f;
  if (tid < 64) ts = sacc[2*tid] + sacc[128 + 2*tid];
  __syncthreads();
  sacc[tid] = bq;
  __syncthreads();
  if (tid < 64){
    g_part[blockIdx.x*128 + tid]      = ts;
    g_part[blockIdx.x*128 + 64 + tid] = sacc[2*tid] + sacc[128 + 2*tid];
  }
  __threadfence();
  __shared__ bool lastb;
  if (tid == 0){
    lastb = (atomicAdd(&g_bncnt, 1) == GOUT-1);
    if (lastb) g_bncnt = 0;
  }
  __syncthreads();
  if (lastb && tid < 64){
    float ss = 0.f, qq = 0.f;
    #pragma unroll 8
    for (int bb = 0; bb < GOUT; bb++){
      ss += __ldcg(&g_part[bb*128 + tid]);
      qq += __ldcg(&g_part[bb*128 + 64 + tid]);
    }
    const float inv = 1.f/(float)NN;
    float mean = ss*inv;
    float var  = qq*inv - mean*mean;
    float rstd = rsqrtf(var + 1e-5f);
    float scv = rstd*gam[tid];
    g_bnscale[tid] = scv;
    g_bnshift[tid] = bet[tid] - mean*scv;
  }
}

// ---------------- MLP1 + heads fused (BN3 at load, hidden never stored) ------
__global__ void __launch_bounds__(256) k_mlp1h(const float* __restrict__ x,
                                               const float* __restrict__ W,
                                               const float* __restrict__ b,
                                               const float* __restrict__ W2,
                                               const float* __restrict__ b2,
                                               const float* __restrict__ pW,
                                               const float* __restrict__ pb,
                                               const float* __restrict__ vW,
                                               const float* __restrict__ vb,
                                               float* __restrict__ out){
  __shared__ float sq[64], sv[64], scst[2];
  __shared__ __align__(16) float sh[4][72];
  __shared__ float spart[8][2];
  int tid = threadIdx.x;
  int j = tid & 63, g = tid >> 6;
  if (tid < 128){
    int k = tid & 63;
    const float* hv = (tid < 64) ? pW : vW;
    const float* row = W2 + k*64;
    float acc = 0.f;
    #pragma unroll 16
    for (int c = 0; c < 64; c++) acc += row[c]*hv[c];
    if (tid < 64) sq[k] = acc; else sv[k] = acc;
  } else if (tid == 128){
    float a = 0.f, c = 0.f;
    #pragma unroll 16
    for (int jj = 0; jj < 64; jj++){ a += b2[jj]*pW[jj]; c += b2[jj]*vW[jj]; }
    scst[0] = a + pb[0];
    scst[1] = c + vb[0];
  }
  ull wp[34];
  #pragma unroll
  for (int k2 = 0; k2 < 34; k2++)
    wp[k2] = pk2(W[(2*k2)*64 + j], W[(2*k2+1)*64 + j]);
  float w68 = W[68*64 + j];
  float bj = b[j];
  float4 sc4, sh4;
  if (j < 16){
    sc4 = ((const float4*)g_bnscale)[j];
    sh4 = ((const float4*)g_bnshift)[j];
  }
  for (int n0 = blockIdx.x*4; n0 < NN; n0 += gridDim.x*4){
    int n = n0 + g;
    if (n < NN){
      if (j < 16){
        float4 v = ((const float4*)(g_buf64 + (size_t)n*64))[j];
        v.x = fmaxf(fmaf(v.x, sc4.x, sh4.x), 0.f);
        v.y = fmaxf(fmaf(v.y, sc4.y, sh4.y), 0.f);
        v.z = fmaxf(fmaf(v.z, sc4.z, sh4.z), 0.f);
        v.w = fmaxf(fmaf(v.w, sc4.w, sh4.w), 0.f);
        ((float4*)sh[g])[j] = v;
      }
      if (j >= 16 && j < 21) sh[g][48 + j] = x[(size_t)n*16 + (j - 7)];  // ctx = x[:,9:14]
    }
    __syncthreads();
    float lp = 0.f, vp = 0.f;
    {
      ull a0 = 0ull, a1 = 0ull;
      const ull* yp = (const ull*)sh[g];
      #pragma unroll
      for (int k2 = 0; k2 < 34; k2 += 2){
        FMA2(a0, yp[k2],   wp[k2],   a0);
        FMA2(a1, yp[k2+1], wp[k2+1], a1);
      }
      float l0,h0,l1,h1; upk2(l0,h0,a0); upk2(l1,h1,a1);
      float t = fmaxf((l0+h0)+(l1+h1) + sh[g][68]*w68 + bj, 0.f);
      if (n < NN){ lp = t*sq[j]; vp = t*sv[j]; }
    }
    #pragma unroll
    for (int o = 16; o; o >>= 1){
      lp += __shfl_xor_sync(0xffffffffu, lp, o);
      vp += __shfl_xor_sync(0xffffffffu, vp, o);
    }
    int w = tid >> 5;
    if ((tid & 31) == 0){ spart[w][0] = lp; spart[w][1] = vp; }
    __syncthreads();
    if (tid < 4){
      int nn = n0 + tid;
      if (nn < NN){
        out[nn]      = spart[2*tid][0] + spart[2*tid+1][0] + scst[0];
        out[NN + nn] = spart[2*tid][1] + spart[2*tid+1][1] + scst[1];
      }
    }
    __syncthreads();
  }
}

// ---------------- launch -----------------------------------------------------
extern "C" void kernel_launch(void* const* d_in, const int* in_sizes, int n_in,
                              void* d_out, int out_size){
  const float* x   = (const float*)d_in[0];
  const int*   ei  = (const int*)  d_in[1];
  const float* W1  = (const float*)d_in[2];
  const float* as1 = (const float*)d_in[3];
  const float* ad1 = (const float*)d_in[4];
  const float* b1  = (const float*)d_in[5];
  const float* g1  = (const float*)d_in[6];
  const float* be1 = (const float*)d_in[7];
  const float* W2  = (const float*)d_in[8];
  const float* as2 = (const float*)d_in[9];
  const float* ad2 = (const float*)d_in[10];
  const float* b2  = (const float*)d_in[11];
  const float* g2  = (const float*)d_in[12];
  const float* be2 = (const float*)d_in[13];
  const float* W3  = (const float*)d_in[14];
  const float* as3 = (const float*)d_in[15];
  const float* ad3 = (const float*)d_in[16];
  const float* b3  = (const float*)d_in[17];
  const float* g3  = (const float*)d_in[18];
  const float* be3 = (const float*)d_in[19];
  const float* mW1 = (const float*)d_in[20];
  const float* mb1 = (const float*)d_in[21];
  const float* mW2 = (const float*)d_in[22];
  const float* mb2 = (const float*)d_in[23];
  const float* pW  = (const float*)d_in[24];
  const float* pb  = (const float*)d_in[25];
  const float* vW  = (const float*)d_in[26];
  const float* vb  = (const float*)d_in[27];
  float* out = (float*)d_out;

  const int TB = 256;
  const int gE   = (EE + TB - 1)/TB;
  const int gN   = (NN + TB - 1)/TB;
  const int gGrp = (NN*16 + TB - 1)/TB;   // 16-lane group per node
  const int gMlp = 1184;

  k_attcount<<<gE, TB>>>(ei, x, W1, as1, ad1);   // 0
  k_scanall<<<NB1, TB>>>();                      // 1
  k_scatter<<<gE, TB>>>(ei);                     // 2

  // layer 1 (D=16, raw x)
  k_agg16<<<gGrp, TB>>>(x);                      // 3  <- profiled
  k_out<16><<<GOUT, TB>>>(W1, b1, g1, be1);      // 4

  // layer 2 (D=64)
  k_att2<<<gN, TB>>>(W2, as2, ad2);              // 5
  k_agg64<<<gGrp, TB>>>();                       // 6
  k_out<64><<<GOUT, TB>>>(W2, b2, g2, be2);      // 7

  // layer 3
  k_att2<<<gN, TB>>>(W3, as3, ad3);              // 8
  k_agg64<<<gGrp, TB>>>();                       // 9
  k_out<64><<<GOUT, TB>>>(W3, b3, g3, be3);      // 10

  // MLP + heads (fused)
  k_mlp1h<<<gMlp, TB>>>(x, mW1, mb1, mW2, mb2, pW, pb, vW, vb, out);  // 11
}

// round 17
// speedup vs baseline: 1.1353x; 1.1353x over previous
#include <cuda_runtime.h>
#include <math.h>

#define NN 100000
#define EE 1000000
#define NB1 98     // ceil(NN/1024)
#define GOUT 592   // grid for k_out

typedef unsigned long long ull;

// ---------------- scratch (static device globals; no allocation) -------------
__device__ float  g_z[(size_t)NN*128];     // aggregated per-head features
__device__ float  g_buf64[(size_t)NN*64];  // layer output (pre-BN)
__device__ float  g_x64[(size_t)NN*64];    // normalized features x' (layers 2,3)
__device__ float  g_as[NN*2];              // per-node src scores
__device__ float4 g_att[NN];               // (as0, as1, ad0, ad1) per node
__device__ int    g_deg[NN];               // zero-init; re-zeroed by k_scatter
__device__ int    g_off[NN];
__device__ int    g_cursor[NN];
__device__ int    g_esrc[EE];
__device__ int    g_bsum[128];
__device__ float  g_part[GOUT*128];        // BN partials per k_out block
__device__ float  g_bnscale[64];
__device__ float  g_bnshift[64];
__device__ int    g_bncnt;
__device__ int    g_scancnt;
__device__ int    g_scandone;

__device__ __forceinline__ float lrelu(float v){ return v > 0.f ? v : 0.2f*v; }

__device__ __forceinline__ ull pk2(float lo, float hi){
  ull u; asm("mov.b64 %0, {%1, %2};" : "=l"(u) : "f"(lo), "f"(hi)); return u;
}
__device__ __forceinline__ void upk2(float& lo, float& hi, ull u){
  asm("mov.b64 {%0, %1}, %2;" : "=f"(lo), "=f"(hi) : "l"(u));
}
#define FMA2(d, a, b, c) \
  asm("fma.rn.f32x2 %0, %1, %2, %3;" : "=l"(d) : "l"(a), "l"(b), "l"(c))

// ---------------- fused: degree count + layer-1 attention scores -------------
__global__ void __launch_bounds__(256) k_attcount(const int* __restrict__ ei,
                                                  const float* __restrict__ x,
                                                  const float* __restrict__ W,
                                                  const float* __restrict__ as_,
                                                  const float* __restrict__ ad_){
  __shared__ float swa[2][16], swd[2][16];
  int tid = threadIdx.x;
  int e = blockIdx.x*blockDim.x + tid;
  bool doatt = (e < NN);
  if (doatt && tid < 64){
    int h = (tid >> 4) & 1;
    int k = tid & 15;
    const float* att = (tid < 32) ? as_ : ad_;
    const float* wrow = W + k*128 + h*64;
    float acc = 0.f;
    #pragma unroll 16
    for (int c = 0; c < 64; c++) acc += wrow[c]*att[h*64 + c];
    if (tid < 32) swa[h][k] = acc; else swd[h][k] = acc;
  }
  if (e < EE) atomicAdd(&g_deg[ei[EE + e]], 1);
  if (!doatt) return;
  __syncthreads();
  int n = e;
  float s0 = 0.f, s1 = 0.f, d0 = 0.f, d1 = 0.f;
  const float4* xr = (const float4*)(x + (size_t)n*16);
  #pragma unroll
  for (int q = 0; q < 4; q++){
    float4 v = xr[q];
    int k = 4*q;
    s0 += v.x*swa[0][k] + v.y*swa[0][k+1] + v.z*swa[0][k+2] + v.w*swa[0][k+3];
    s1 += v.x*swa[1][k] + v.y*swa[1][k+1] + v.z*swa[1][k+2] + v.w*swa[1][k+3];
    d0 += v.x*swd[0][k] + v.y*swd[0][k+1] + v.z*swd[0][k+2] + v.w*swd[0][k+3];
    d1 += v.x*swd[1][k] + v.y*swd[1][k+1] + v.z*swd[1][k+2] + v.w*swd[1][k+3];
  }
  ((float2*)g_as)[n] = make_float2(s0, s1);
  g_att[n] = make_float4(s0, s1, d0, d1);
}

// ---------------- fused scan: local scan + spin-wait grid sync + prefix ------
__global__ void __launch_bounds__(256) k_scanall(){
  __shared__ int s[256];
  __shared__ int swarp[8];
  int tid = threadIdx.x;
  int b = blockIdx.x;
  int base = b*1024 + tid*4;
  int v[4]; int loc = 0;
  #pragma unroll
  for (int i = 0; i < 4; i++){ int idx = base + i; v[i] = (idx < NN) ? g_deg[idx] : 0; loc += v[i]; }
  s[tid] = loc; __syncthreads();
  #pragma unroll
  for (int d = 1; d < 256; d <<= 1){
    int t = (tid >= d) ? s[tid-d] : 0; __syncthreads();
    s[tid] += t; __syncthreads();
  }
  int run = (tid == 0) ? 0 : s[tid-1];
  #pragma unroll
  for (int i = 0; i < 4; i++){ run += v[i]; int idx = base + i; if (idx < NN) g_off[idx] = run; }
  if (tid == 255){
    g_bsum[b] = s[255];
    __threadfence();
    atomicAdd(&g_scancnt, 1);
  }
  if (tid == 0){
    while (atomicAdd(&g_scancnt, 0) < NB1) { }
  }
  __syncthreads();
  {
    int vv = (tid < b) ? g_bsum[tid] : 0;
    #pragma unroll
    for (int o = 16; o; o >>= 1) vv += __shfl_xor_sync(0xffffffffu, vv, o);
    if ((tid & 31) == 0) swarp[tid >> 5] = vv;
  }
  __syncthreads();
  int pre = swarp[0] + swarp[1] + swarp[2] + swarp[3];
  #pragma unroll
  for (int i = 0; i < 4; i++){
    int idx = base + i;
    if (idx < NN){
      int off = g_off[idx] + pre;
      g_off[idx] = off;
      g_cursor[idx] = off - g_deg[idx];
    }
  }
  __syncthreads();
  if (tid == 0){
    int d = atomicAdd(&g_scandone, 1);
    if (d == NB1-1){ g_scancnt = 0; g_scandone = 0; }
  }
}

__global__ void k_scatter(const int* __restrict__ ei){
  int e = blockIdx.x*blockDim.x + threadIdx.x;
  if (e < EE){
    int s = ei[e], d = ei[EE + e];
    int pos = atomicAdd(&g_cursor[d], 1);
    g_esrc[pos] = s;
  }
  if (e < NN) g_deg[e] = 0;
}

// ---------------- attention scores (layers 2,3): thread-per-node, BN in regs -
// Also writes the normalized x' row to g_x64 for the BN-free gather.
__global__ void __launch_bounds__(256) k_att2(const float* __restrict__ W,
                                              const float* __restrict__ as_,
                                              const float* __restrict__ ad_){
  __shared__ float swa[2][64], swd[2][64];
  __shared__ float sbs[64], sbh[64];
  int tid = threadIdx.x;
  {
    int h = (tid >> 6) & 1;
    int k = tid & 63;
    const float* att = (tid < 128) ? as_ : ad_;
    const float* wrow = W + k*128 + h*64;
    float acc = 0.f;
    #pragma unroll 16
    for (int c = 0; c < 64; c++) acc += wrow[c]*att[h*64 + c];
    if (tid < 128) swa[h][k] = acc; else swd[h][k] = acc;
    if (tid < 64){ sbs[tid] = g_bnscale[tid]; sbh[tid] = g_bnshift[tid]; }
  }
  __syncthreads();
  int n = blockIdx.x*blockDim.x + tid;
  if (n >= NN) return;
  float s0 = 0.f, s1 = 0.f, d0 = 0.f, d1 = 0.f;
  const float4* xr = (const float4*)(g_buf64 + (size_t)n*64);
  float4* xw = (float4*)(g_x64 + (size_t)n*64);
  #pragma unroll
  for (int q = 0; q < 16; q++){
    float4 v = xr[q];
    int k = 4*q;
    v.x = fmaxf(fmaf(v.x, sbs[k],   sbh[k]),   0.f);
    v.y = fmaxf(fmaf(v.y, sbs[k+1], sbh[k+1]), 0.f);
    v.z = fmaxf(fmaf(v.z, sbs[k+2], sbh[k+2]), 0.f);
    v.w = fmaxf(fmaf(v.w, sbs[k+3], sbh[k+3]), 0.f);
    xw[q] = v;
    s0 += v.x*swa[0][k] + v.y*swa[0][k+1] + v.z*swa[0][k+2] + v.w*swa[0][k+3];
    s1 += v.x*swa[1][k] + v.y*swa[1][k+1] + v.z*swa[1][k+2] + v.w*swa[1][k+3];
    d0 += v.x*swd[0][k] + v.y*swd[0][k+1] + v.z*swd[0][k+2] + v.w*swd[0][k+3];
    d1 += v.x*swd[1][k] + v.y*swd[1][k+1] + v.z*swd[1][k+2] + v.w*swd[1][k+3];
  }
  ((float2*)g_as)[n] = make_float2(s0, s1);
  g_att[n] = make_float4(s0, s1, d0, d1);
}

// ---------------- GAT aggregation: single-pass softmax, smem-staged triples,
//                  FIXED 16-iter unrolled gather -----------------------------
__global__ void __launch_bounds__(256) k_agg16(const float* __restrict__ x){
  __shared__ __align__(16) float4 sedge[16][16];
  int t = blockIdx.x*blockDim.x + threadIdx.x;
  int n = t >> 4, lane = t & 15;
  if (n >= NN) return;
  const unsigned gm = 0xFFFFu << (threadIdx.x & 16);
  int grp = threadIdx.x >> 4;
  int start = n ? g_off[n-1] : 0;
  int end   = g_off[n];
  float4 attn = g_att[n];
  float ad0 = attn.z, ad1 = attn.w;
  float es0 = lrelu(attn.x + ad0);
  float es1 = lrelu(attn.y + ad1);
  float vs = x[(size_t)n*16 + lane];
  ull y01 = pk2(vs, vs);
  float dacc0 = 0.f, dacc1 = 0.f;

  for (int base = start; base < end; base += 16){
    int cnt = min(16, end - base);
    int s = n; float w0 = 0.f, w1 = 0.f;
    if (lane < cnt){
      s = g_esrc[base + lane];
      float2 a = ((const float2*)g_as)[s];
      w0 = __expf(lrelu(a.x + ad0) - es0);
      w1 = __expf(lrelu(a.y + ad1) - es1);
      dacc0 += w0; dacc1 += w1;
    }
    sedge[grp][lane] = make_float4(__int_as_float(s), w0, w1, 0.f);
    __syncwarp(gm);
    #pragma unroll
    for (int k = 0; k < 16; k++){
      float4 tr = sedge[grp][k];
      int sk = __float_as_int(tr.x);
      float v = x[(size_t)sk*16 + lane];
      FMA2(y01, pk2(v, v), pk2(tr.y, tr.z), y01);
    }
    __syncwarp(gm);
  }
  #pragma unroll
  for (int o = 8; o; o >>= 1){
    dacc0 += __shfl_xor_sync(gm, dacc0, o, 16);
    dacc1 += __shfl_xor_sync(gm, dacc1, o, 16);
  }
  float den0 = 1.f + dacc0 + 1e-16f;
  float den1 = 1.f + dacc1 + 1e-16f;
  float y0, y1; upk2(y0, y1, y01);
  float* zr = g_z + (size_t)n*32;
  zr[lane]      = y0/den0;
  zr[16 + lane] = y1/den1;
}

__global__ void __launch_bounds__(256) k_agg64(){
  __shared__ __align__(16) float4 sedge[16][16];
  int t = blockIdx.x*blockDim.x + threadIdx.x;
  int n = t >> 4, lane = t & 15;
  if (n >= NN) return;
  const unsigned gm = 0xFFFFu << (threadIdx.x & 16);
  int grp = threadIdx.x >> 4;
  int start = n ? g_off[n-1] : 0;
  int end   = g_off[n];
  float4 attn = g_att[n];
  float ad0 = attn.z, ad1 = attn.w;
  float es0 = lrelu(attn.x + ad0);
  float es1 = lrelu(attn.y + ad1);
  ulonglong2 vsl = ((const ulonglong2*)(g_x64 + (size_t)n*64))[lane];
  ull y0a = vsl.x, y0b = vsl.y;
  ull y1a = vsl.x, y1b = vsl.y;
  float dacc0 = 0.f, dacc1 = 0.f;

  for (int base = start; base < end; base += 16){
    int cnt = min(16, end - base);
    int s = n; float w0 = 0.f, w1 = 0.f;
    if (lane < cnt){
      s = g_esrc[base + lane];
      float2 a = ((const float2*)g_as)[s];
      w0 = __expf(lrelu(a.x + ad0) - es0);
      w1 = __expf(lrelu(a.y + ad1) - es1);
      dacc0 += w0; dacc1 += w1;
    }
    sedge[grp][lane] = make_float4(__int_as_float(s), w0, w1, 0.f);
    __syncwarp(gm);
    #pragma unroll 4
    for (int k = 0; k < 16; k++){
      float4 tr = sedge[grp][k];
      int sk = __float_as_int(tr.x);
      ull w0p = pk2(tr.y, tr.y);
      ull w1p = pk2(tr.z, tr.z);
      ulonglong2 v = ((const ulonglong2*)(g_x64 + (size_t)sk*64))[lane];
      FMA2(y0a, v.x, w0p, y0a); FMA2(y0b, v.y, w0p, y0b);
      FMA2(y1a, v.x, w1p, y1a); FMA2(y1b, v.y, w1p, y1b);
    }
    __syncwarp(gm);
  }
  #pragma unroll
  for (int o = 8; o; o >>= 1){
    dacc0 += __shfl_xor_sync(gm, dacc0, o, 16);
    dacc1 += __shfl_xor_sync(gm, dacc1, o, 16);
  }
  float den0 = 1.f + dacc0 + 1e-16f;
  float den1 = 1.f + dacc1 + 1e-16f;
  float i0 = 1.f/den0, i1 = 1.f/den1;
  float l, h;
  float4 o0, o1;
  upk2(l, h, y0a); o0.x = l*i0; o0.y = h*i0;
  upk2(l, h, y0b); o0.z = l*i0; o0.w = h*i0;
  upk2(l, h, y1a); o1.x = l*i1; o1.y = h*i1;
  upk2(l, h, y1b); o1.z = l*i1; o1.w = h*i1;
  float4* zr = (float4*)(g_z + (size_t)n*128);
  zr[lane]      = o0;
  zr[16 + lane] = o1;
}

// ---------------- output transform: 8 nodes per barrier pair (R13 design) ----
// BN finalize tail parallelized over 256 threads (2 threads per stat value).
template<int D>
__global__ void __launch_bounds__(256) k_out(const float* __restrict__ W,
                                             const float* __restrict__ b,
                                             const float* __restrict__ gam,
                                             const float* __restrict__ bet){
  int tid = threadIdx.x;
  int g   = tid >> 7;
  int idx = tid & 127;
  int j   = idx >> 1;
  int hb  = idx & 1;
  ull wp[D/2];
  #pragma unroll
  for (int k2 = 0; k2 < D/2; k2++)
    wp[k2] = pk2(0.5f*W[(2*k2)*128 + hb*64 + j], 0.5f*W[(2*k2+1)*128 + hb*64 + j]);
  float bj = b[j];
  __shared__ __align__(16) float sy[8][2*D];
  __shared__ float sacc[256];
  float bs = 0.f, bq = 0.f;
  const int F4 = D/2;
  for (int n0 = blockIdx.x*8; n0 < NN; n0 += GOUT*8){
    if (tid < 4*D){
      int row = tid / F4;
      int col = tid % F4;
      int n = n0 + row;
      if (n < NN)
        ((float4*)sy[row])[col] = ((const float4*)(g_z + (size_t)n*(2*D)))[col];
    }
    __syncthreads();
    #pragma unroll
    for (int i = 0; i < 4; i++){
      int n = n0 + g*4 + i;
      const ull* yp = (const ull*)(sy[g*4+i] + hb*D);
      ull a0 = 0ull, a1 = 0ull;
      #pragma unroll
      for (int k2 = 0; k2 < D/2; k2 += 2){
        FMA2(a0, yp[k2],   wp[k2],   a0);
        FMA2(a1, yp[k2+1], wp[k2+1], a1);
      }
      float l0,h0,l1,h1; upk2(l0,h0,a0); upk2(l1,h1,a1);
      float partial = (l0+h0)+(l1+h1);
      float comb = partial + __shfl_xor_sync(0xffffffffu, partial, 1);
      if (hb == 0 && n < NN){
        float r = comb + bj;
        g_buf64[(size_t)n*64 + j] = r;
        bs += r; bq += r*r;
      }
    }
    __syncthreads();
  }
  sacc[tid] = bs;
  __syncthreads();
  float ts = 0.f;
  if (tid < 64) ts = sacc[2*tid] + sacc[128 + 2*tid];
  __syncthreads();
  sacc[tid] = bq;
  __syncthreads();
  if (tid < 64){
    g_part[blockIdx.x*128 + tid]      = ts;
    g_part[blockIdx.x*128 + 64 + tid] = sacc[2*tid] + sacc[128 + 2*tid];
  }
  __threadfence();
  __shared__ bool lastb;
  if (tid == 0){
    lastb = (atomicAdd(&g_bncnt, 1) == GOUT-1);
    if (lastb) g_bncnt = 0;
  }
  __syncthreads();
  if (lastb){
    // parallel finalize: 256 threads, 2 per stat value (c in [0,128)),
    // each covers half of the GOUT blocks.
    int c    = tid & 127;
    int half = tid >> 7;
    int b0 = half*(GOUT/2), b1 = b0 + (GOUT/2);
    float acc = 0.f;
    #pragma unroll 8
    for (int bb = b0; bb < b1; bb++)
      acc += __ldcg(&g_part[bb*128 + c]);
    sacc[tid] = acc;
    __syncthreads();
    if (tid < 64){
      float ss = sacc[tid]      + sacc[128 + tid];        // sum halves, c=tid
      float qq = sacc[64 + tid] + sacc[192 + tid];        // sumsq halves, c=64+tid
      const float inv = 1.f/(float)NN;
      float mean = ss*inv;
      float var  = qq*inv - mean*mean;
      float rstd = rsqrtf(var + 1e-5f);
      float scv = rstd*gam[tid];
      g_bnscale[tid] = scv;
      g_bnshift[tid] = bet[tid] - mean*scv;
    }
  }
}

// ---------------- MLP1 + heads fused (BN3 at load, hidden never stored) ------
__global__ void __launch_bounds__(256) k_mlp1h(const float* __restrict__ x,
                                               const float* __restrict__ W,
                                               const float* __restrict__ b,
                                               const float* __restrict__ W2,
                                               const float* __restrict__ b2,
                                               const float* __restrict__ pW,
                                               const float* __restrict__ pb,
                                               const float* __restrict__ vW,
                                               const float* __restrict__ vb,
                                               float* __restrict__ out){
  __shared__ float sq[64], sv[64], scst[2];
  __shared__ __align__(16) float sh[4][72];
  __shared__ float spart[8][2];
  int tid = threadIdx.x;
  int j = tid & 63, g = tid >> 6;
  if (tid < 128){
    int k = tid & 63;
    const float* hv = (tid < 64) ? pW : vW;
    const float* row = W2 + k*64;
    float acc = 0.f;
    #pragma unroll 16
    for (int c = 0; c < 64; c++) acc += row[c]*hv[c];
    if (tid < 64) sq[k] = acc; else sv[k] = acc;
  } else if (tid == 128){
    float a = 0.f, c = 0.f;
    #pragma unroll 16
    for (int jj = 0; jj < 64; jj++){ a += b2[jj]*pW[jj]; c += b2[jj]*vW[jj]; }
    scst[0] = a + pb[0];
    scst[1] = c + vb[0];
  }
  ull wp[34];
  #pragma unroll
  for (int k2 = 0; k2 < 34; k2++)
    wp[k2] = pk2(W[(2*k2)*64 + j], W[(2*k2+1)*64 + j]);
  float w68 = W[68*64 + j];
  float bj = b[j];
  float4 sc4, sh4;
  if (j < 16){
    sc4 = ((const float4*)g_bnscale)[j];
    sh4 = ((const float4*)g_bnshift)[j];
  }
  for (int n0 = blockIdx.x*4; n0 < NN; n0 += gridDim.x*4){
    int n = n0 + g;
    if (n < NN){
      if (j < 16){
        float4 v = ((const float4*)(g_buf64 + (size_t)n*64))[j];
        v.x = fmaxf(fmaf(v.x, sc4.x, sh4.x), 0.f);
        v.y = fmaxf(fmaf(v.y, sc4.y, sh4.y), 0.f);
        v.z = fmaxf(fmaf(v.z, sc4.z, sh4.z), 0.f);
        v.w = fmaxf(fmaf(v.w, sc4.w, sh4.w), 0.f);
        ((float4*)sh[g])[j] = v;
      }
      if (j >= 16 && j < 21) sh[g][48 + j] = x[(size_t)n*16 + (j - 7)];  // ctx = x[:,9:14]
    }
    __syncthreads();
    float lp = 0.f, vp = 0.f;
    {
      ull a0 = 0ull, a1 = 0ull;
      const ull* yp = (const ull*)sh[g];
      #pragma unroll
      for (int k2 = 0; k2 < 34; k2 += 2){
        FMA2(a0, yp[k2],   wp[k2],   a0);
        FMA2(a1, yp[k2+1], wp[k2+1], a1);
      }
      float l0,h0,l1,h1; upk2(l0,h0,a0); upk2(l1,h1,a1);
      float t = fmaxf((l0+h0)+(l1+h1) + sh[g][68]*w68 + bj, 0.f);
      if (n < NN){ lp = t*sq[j]; vp = t*sv[j]; }
    }
    #pragma unroll
    for (int o = 16; o; o >>= 1){
      lp += __shfl_xor_sync(0xffffffffu, lp, o);
      vp += __shfl_xor_sync(0xffffffffu, vp, o);
    }
    int w = tid >> 5;
    if ((tid & 31) == 0){ spart[w][0] = lp; spart[w][1] = vp; }
    __syncthreads();
    if (tid < 4){
      int nn = n0 + tid;
      if (nn < NN){
        out[nn]      = spart[2*tid][0] + spart[2*tid+1][0] + scst[0];
        out[NN + nn] = spart[2*tid][1] + spart[2*tid+1][1] + scst[1];
      }
    }
    __syncthreads();
  }
}

// ---------------- launch -----------------------------------------------------
extern "C" void kernel_launch(void* const* d_in, const int* in_sizes, int n_in,
                              void* d_out, int out_size){
  const float* x   = (const float*)d_in[0];
  const int*   ei  = (const int*)  d_in[1];
  const float* W1  = (const float*)d_in[2];
  const float* as1 = (const float*)d_in[3];
  const float* ad1 = (const float*)d_in[4];
  const float* b1  = (const float*)d_in[5];
  const float* g1  = (const float*)d_in[6];
  const float* be1 = (const float*)d_in[7];
  const float* W2  = (const float*)d_in[8];
  const float* as2 = (const float*)d_in[9];
  const float* ad2 = (const float*)d_in[10];
  const float* b2  = (const float*)d_in[11];
  const float* g2  = (const float*)d_in[12];
  const float* be2 = (const float*)d_in[13];
  const float* W3  = (const float*)d_in[14];
  const float* as3 = (const float*)d_in[15];
  const float* ad3 = (const float*)d_in[16];
  const float* b3  = (const float*)d_in[17];
  const float* g3  = (const float*)d_in[18];
  const float* be3 = (const float*)d_in[19];
  const float* mW1 = (const float*)d_in[20];
  const float* mb1 = (const float*)d_in[21];
  const float* mW2 = (const float*)d_in[22];
  const float* mb2 = (const float*)d_in[23];
  const float* pW  = (const float*)d_in[24];
  const float* pb  = (const float*)d_in[25];
  const float* vW  = (const float*)d_in[26];
  const float* vb  = (const float*)d_in[27];
  float* out = (float*)d_out;

  const int TB = 256;
  const int gE   = (EE + TB - 1)/TB;
  const int gN   = (NN + TB - 1)/TB;
  const int gGrp = (NN*16 + TB - 1)/TB;   // 16-lane group per node
  const int gMlp = 1184;

  k_attcount<<<gE, TB>>>(ei, x, W1, as1, ad1);   // 0
  k_scanall<<<NB1, TB>>>();                      // 1
  k_scatter<<<gE, TB>>>(ei);                     // 2

  // layer 1 (D=16, raw x)
  k_agg16<<<gGrp, TB>>>(x);                      // 3  <- profiled
  k_out<16><<<GOUT, TB>>>(W1, b1, g1, be1);      // 4

  // layer 2 (D=64)
  k_att2<<<gN, TB>>>(W2, as2, ad2);              // 5
  k_agg64<<<gGrp, TB>>>();                       // 6
  k_out<64><<<GOUT, TB>>>(W2, b2, g2, be2);      // 7

  // layer 3
  k_att2<<<gN, TB>>>(W3, as3, ad3);              // 8
  k_agg64<<<gGrp, TB>>>();                       // 9
  k_out<64><<<GOUT, TB>>>(W3, b3, g3, be3);      // 10

  // MLP + heads (fused)
  k_mlp1h<<<gMlp, TB>>>(x, mW1, mb1, mW2, mb2, pW, pb, vW, vb, out);  // 11
}